// round 11
// baseline (speedup 1.0000x reference)
#include <cuda_runtime.h>
#include <math.h>

#define NB 16
#define H 512
#define W 512
#define KR 15
#define MUF 5.0f
#define QS 8.0f                       // vsum quant scale
#define BOXSCALE (1.0f/(961.0f*8.0f)) // KKINV / QS
#define MINV (1.0f/255.0f)            // mask dequant scale
#define RPB 16                        // rows per block in vert kernel
#define ROWS_PER_BLK 4                // rows per block in main kernel
#define VSTRIDE 544                   // 16B pad | 512 cols | 16B pad
#define NBLK_B (NB * H / ROWS_PER_BLK)   // 2048

// zero-initialized; vsum pad bytes are never written so they stay 0 forever
__device__ unsigned char g_vu8[NB * H * VSTRIDE];   // ~4.45 MB vertical box sums (u8)
__device__ unsigned char g_mu8[NB * H * W];         // 4.2 MB quantized mask
__device__ float4 g_part4[NBLK_B];                  // per-block partials
__device__ unsigned int g_count;                    // zero-init; self-resetting

// ===== Kernel A: vertical sliding box sum (u8 out) + mask u8 quantization =====
// 256 threads, 2 cols/thread via float2. While initializing the window it also
// emits the quantized mask for its own 16 output rows (each row covered once).
__global__ void __launch_bounds__(256) vert_kernel(const float* __restrict__ mask) {
    const int segs = H / RPB;        // 32
    const int b  = blockIdx.x / segs;
    const int r0 = (blockIdx.x % segs) * RPB;
    const int t  = threadIdx.x;      // 0..255, cols 2t, 2t+1

    const float2* mb2 = (const float2*)(mask + (size_t)b * H * W);
    unsigned short* vb = (unsigned short*)(g_vu8 + (size_t)b * H * VSTRIDE);
    unsigned short* mq = (unsigned short*)(g_mu8 + (size_t)b * H * W);

    // 4-way tree init of window [r0-15, r0+15]; quantize mask rows r0..r0+15
    float ax[4] = {0.f, 0.f, 0.f, 0.f};
    float ay[4] = {0.f, 0.f, 0.f, 0.f};
    int lo = r0 - KR; if (lo < 0) lo = 0;
    const int hi = r0 + KR;          // <= 511 always
    int k = 0;
    for (int j = lo; j <= hi; ++j, ++k) {
        float2 v = __ldcg(&mb2[j * (W / 2) + t]);
        ax[k & 3] += v.x; ay[k & 3] += v.y;
        if (j >= r0) {
            unsigned qx = __float2uint_rn(v.x * 255.f);
            unsigned qy = __float2uint_rn(v.y * 255.f);
            __stcg(&mq[j * (W / 2) + t], (unsigned short)(qx | (qy << 8)));
        }
    }
    const float ix = (ax[0] + ax[1]) + (ax[2] + ax[3]);
    const float iy = (ay[0] + ay[1]) + (ay[2] + ay[3]);

    // independent add / sub chains
    float addx = 0.f, addy = 0.f, subx = 0.f, suby = 0.f;
    #pragma unroll
    for (int rr = 0; rr < RPB; ++rr) {
        const int r = r0 + rr;
        float vx = (ix + addx) - subx;
        float vy = (iy + addy) - suby;
        unsigned qx = (unsigned)__float2int_rn(vx * QS);
        unsigned qy = (unsigned)__float2int_rn(vy * QS);
        __stcg(&vb[r * (VSTRIDE / 2) + 8 + t], (unsigned short)(qx | (qy << 8)));
        int ar = r + KR + 1;
        int sr = r - KR;
        if (ar < H) {
            float2 v = __ldcg(&mb2[ar * (W / 2) + t]);
            addx += v.x; addy += v.y;
        }
        if (sr >= 0) {
            float2 v = __ldcg(&mb2[sr * (W / 2) + t]);
            subx += v.x; suby += v.y;
        }
    }
}

// ========== Kernel B: dp4a horizontal box + elementwise + reduce ==========
// 256 threads, 4 rows per block, 64 threads per row, 8 cols per thread.
// vsum row is u8 with 16-byte zero pads: thread u loads bytes 8u..8u+39
// (5 aligned LDG.64) and computes the 31-tap window via dp4a prefix sums.
// mask is read as u8 (1 LDG.64 instead of 2 LDG.128).
__global__ void __launch_bounds__(256, 6)
main_kernel(const float* __restrict__ pred,
            const float* __restrict__ mask,
            float* __restrict__ out) {
    __shared__ float red[32];        // 8 warps x 4 accumulators
    __shared__ float flag;

    const int t    = threadIdx.x;
    const int wid  = t >> 5;
    const int lane = t & 31;
    const int g    = t >> 6;         // row within block 0..3
    const int u    = t & 63;         // thread within row

    const int rowg = blockIdx.x * ROWS_PER_BLK + g;   // global row 0..8191
    const int b = rowg >> 9;
    const int r = rowg & (H - 1);

    // ---- vsum halo loads: bytes 8u .. 8u+39 as 5 aligned uint2 ----
    const uint2* vrow = (const uint2*)(g_vu8 + ((size_t)b * H + r) * VSTRIDE);
    uint2 L0 = vrow[u + 0];
    uint2 L1 = vrow[u + 1];
    uint2 L2 = vrow[u + 2];
    uint2 L3 = vrow[u + 3];
    uint2 L4 = vrow[u + 4];

    // ---- streaming elementwise inputs: u8 mask + fp32 pred ----
    const uint2* mrow = (const uint2*)(g_mu8 + ((size_t)b * H + r) * W);
    const uint2 M = __ldcg(&mrow[u]);                 // 8 mask bytes
    const size_t predOff = (((size_t)b * 2 + 1) * H + r) * W;
    const float4* prow = (const float4*)(pred + predOff);
    float4 p4[2];
    p4[0] = __ldcg(&prow[u * 2 + 0]);
    p4[1] = __ldcg(&prow[u * 2 + 1]);

    // ---- integer prefix over 40 bytes via dp4a ----
    unsigned w0 = L0.x, w1 = L0.y, w8 = L4.x, w9 = L4.y;
    const unsigned M1 = 0x01010101u;
    unsigned wp1 = __dp4a(w0, M1, 0u);
    unsigned wp2 = __dp4a(w1, M1, wp1);
    unsigned wp3 = __dp4a(L1.x, M1, wp2);
    unsigned wp4 = __dp4a(L1.y, M1, wp3);
    unsigned wp5 = __dp4a(L2.x, M1, wp4);
    unsigned wp6 = __dp4a(L2.y, M1, wp5);
    unsigned wp7 = __dp4a(L3.x, M1, wp6);
    unsigned wp8 = __dp4a(L3.y, M1, wp7);
    unsigned wp9 = __dp4a(w8, M1, wp8);
    (void)wp3; (void)wp4; (void)wp5; (void)wp6; (void)wp7;

    // S_inc[k] = sum of bytes 0..k ; need k = 0..7 and k = 31..38
    unsigned loS[8], hiS[8];
    loS[0] = __dp4a(w0, 0x00000001u, 0u);
    loS[1] = __dp4a(w0, 0x00000101u, 0u);
    loS[2] = __dp4a(w0, 0x00010101u, 0u);
    loS[3] = wp1;
    loS[4] = __dp4a(w1, 0x00000001u, wp1);
    loS[5] = __dp4a(w1, 0x00000101u, wp1);
    loS[6] = __dp4a(w1, 0x00010101u, wp1);
    loS[7] = wp2;
    hiS[0] = wp8;                                    // k=31
    hiS[1] = __dp4a(w8, 0x00000001u, wp8);           // k=32
    hiS[2] = __dp4a(w8, 0x00000101u, wp8);
    hiS[3] = __dp4a(w8, 0x00010101u, wp8);
    hiS[4] = wp9;                                    // k=35
    hiS[5] = __dp4a(w9, 0x00000001u, wp9);
    hiS[6] = __dp4a(w9, 0x00000101u, wp9);
    hiS[7] = __dp4a(w9, 0x00010101u, wp9);

    // ---- unpack mask bytes to floats ----
    float mv[8];
    mv[0] = (float)( M.x        & 255u) * MINV;
    mv[1] = (float)((M.x >>  8) & 255u) * MINV;
    mv[2] = (float)((M.x >> 16) & 255u) * MINV;
    mv[3] = (float)( M.x >> 24        ) * MINV;
    mv[4] = (float)( M.y        & 255u) * MINV;
    mv[5] = (float)((M.y >>  8) & 255u) * MINV;
    mv[6] = (float)((M.y >> 16) & 255u) * MINV;
    mv[7] = (float)( M.y >> 24        ) * MINV;

    float pv[8] = {p4[0].x, p4[0].y, p4[0].z, p4[0].w,
                   p4[1].x, p4[1].y, p4[1].z, p4[1].w};

    float a0 = 0.f, a1 = 0.f, a2 = 0.f, a3 = 0.f;
    #pragma unroll
    for (int i = 0; i < 8; ++i) {
        float box  = (float)(int)(hiS[i] - loS[i]) * BOXSCALE;
        float m    = mv[i];
        float p    = pv[i];
        float weit = 1.0f + MUF * fabsf(box - m);

        float eexp = __expf(-fabsf(p));                            // MUFU.EX2
        float bce  = fmaxf(p, 0.0f) - p * m + __logf(1.0f + eexp); // MUFU.LG2
        float rcp  = __fdividef(1.0f, 1.0f + eexp);                // MUFU.RCP
        float ps   = (p >= 0.0f) ? rcp : eexp * rcp;               // sigmoid(p)

        a0 += weit * bce;
        a1 += weit;
        float wps = weit * ps;
        a2 += wps * m;
        a3 += wps + weit * m;
    }

    // ---- warp reduction ----
    #pragma unroll
    for (int d = 16; d > 0; d >>= 1) {
        a0 += __shfl_down_sync(0xffffffffu, a0, d);
        a1 += __shfl_down_sync(0xffffffffu, a1, d);
        a2 += __shfl_down_sync(0xffffffffu, a2, d);
        a3 += __shfl_down_sync(0xffffffffu, a3, d);
    }
    if (lane == 0) {
        red[wid * 4 + 0] = a0;
        red[wid * 4 + 1] = a1;
        red[wid * 4 + 2] = a2;
        red[wid * 4 + 3] = a3;
    }
    __syncthreads();

    // ---- cross-warp reduction in warp 0 (shuffle tree) ----
    if (wid == 0) {
        float y = red[lane];                 // lane = w*4 + k, w<8, k<4
        y += __shfl_xor_sync(0xffffffffu, y, 4);
        y += __shfl_xor_sync(0xffffffffu, y, 8);
        y += __shfl_xor_sync(0xffffffffu, y, 16);
        float s0 = __shfl_sync(0xffffffffu, y, 0);
        float s1 = __shfl_sync(0xffffffffu, y, 1);
        float s2 = __shfl_sync(0xffffffffu, y, 2);
        float s3 = __shfl_sync(0xffffffffu, y, 3);
        if (lane == 0) {
            __stcg(&g_part4[blockIdx.x], make_float4(s0, s1, s2, s3));
            unsigned int old;
            asm volatile("atom.acq_rel.gpu.global.add.u32 %0, [%1], %2;"
                         : "=r"(old) : "l"(&g_count), "r"(1u) : "memory");
            flag = (old == NBLK_B - 1) ? 1.f : 0.f;
        }
    }
    __syncthreads();

    // ---------- last block finalizes ----------
    if (flag != 0.f) {
        if (t < 128) {
            const int bb = t >> 3;           // batch 0..15
            const int j  = t & 7;            // chunk 0..7
            float s0 = 0.f, s1 = 0.f, s2 = 0.f, s3 = 0.f;
            const float4* gp = g_part4 + bb * (NBLK_B / NB) + j * 16;
            #pragma unroll
            for (int kk = 0; kk < 16; ++kk) {
                float4 vv = __ldcg(&gp[kk]);
                s0 += vv.x; s1 += vv.y; s2 += vv.z; s3 += vv.w;
            }
            #pragma unroll
            for (int d = 4; d > 0; d >>= 1) {
                s0 += __shfl_down_sync(0xffffffffu, s0, d, 8);
                s1 += __shfl_down_sync(0xffffffffu, s1, d, 8);
                s2 += __shfl_down_sync(0xffffffffu, s2, d, 8);
                s3 += __shfl_down_sync(0xffffffffu, s3, d, 8);
            }
            if (j == 0) {
                float wbce = s0 / s1;
                float wiou = 1.0f - (s2 + 1.0f) / (s3 - s2 + 1.0f);
                red[bb] = wbce + wiou;
            }
        }
        __syncthreads();
        if (t == 0) {
            float s = 0.f;
            #pragma unroll
            for (int kk = 0; kk < NB; ++kk) s += red[kk];
            out[0] = s * (1.0f / NB);
            g_count = 0;                     // self-reset for next graph replay
        }
    }
}

extern "C" void kernel_launch(void* const* d_in, const int* in_sizes, int n_in,
                              void* d_out, int out_size) {
    const float* pred = (const float*)d_in[0];
    const float* mask = (const float*)d_in[1];
    if (n_in >= 2 && in_sizes[0] == NB * H * W && in_sizes[1] == NB * 2 * H * W) {
        mask = (const float*)d_in[0];
        pred = (const float*)d_in[1];
    }
    float* out = (float*)d_out;

    vert_kernel<<<NB * (H / RPB), 256>>>(mask);
    main_kernel<<<NBLK_B, 256>>>(pred, mask, out);
}

// round 12
// speedup vs baseline: 1.0708x; 1.0708x over previous
#include <cuda_runtime.h>
#include <math.h>

#define NB 16
#define H 512
#define W 512
#define KR 15
#define MUF 5.0f
#define QS 8.0f                       // vsum quant scale
#define BOXSCALE (1.0f/(961.0f*8.0f)) // KKINV / QS
#define ROWS 16                       // rows per block
#define VSTRIDE 544                   // 16B pad | 512 cols | 16B pad
#define NBLK (NB * (H / ROWS))        // 512 blocks

__device__ float4 g_part4[NBLK];      // per-block partials
__device__ unsigned int g_count;      // zero-init; self-resetting

__global__ void __launch_bounds__(512)
fused_kernel(const float* __restrict__ pred,
             const float* __restrict__ mask,
             float* __restrict__ out) {
    __shared__ unsigned char s_v[ROWS * VSTRIDE];   // u8 vsums, padded rows (8.7KB)
    __shared__ float red[64];                       // 16 warps x 4
    __shared__ float flag;

    const int t = threadIdx.x;          // 0..511
    const int b  = blockIdx.x >> 5;     // batch
    const int r0 = (blockIdx.x & 31) * ROWS;

    const float* mb = mask + (size_t)b * H * W;
    const float* pb = pred + (size_t)(b * 2 + 1) * H * W;   // channel-1 logits

    // ---- zero smem pads: 16 rows x 8 words (4 left, 4 right) ----
    if (t < 128) {
        const int row = t >> 3;
        const int idx = t & 7;
        const int off = row * VSTRIDE + (idx < 4 ? idx * 4 : 528 + (idx - 4) * 4);
        *(unsigned int*)&s_v[off] = 0u;
    }

    // ================= phase 1: vertical sliding box sum -> smem u8 =========
    {
        const int c = t;                // one column per thread
        // 4-way tree init of window [r0-15, r0+15]
        float a0 = 0.f, a1 = 0.f, a2 = 0.f, a3 = 0.f;
        int lo = r0 - KR; if (lo < 0) lo = 0;
        const int hi = r0 + KR;         // <= 511
        int k = 0;
        for (int j = lo; j <= hi; ++j, ++k) {
            float v = __ldcg(&mb[j * W + c]);
            if ((k & 3) == 0) a0 += v;
            else if ((k & 3) == 1) a1 += v;
            else if ((k & 3) == 2) a2 += v;
            else a3 += v;
        }
        const float ix = (a0 + a1) + (a2 + a3);

        // independent add / sub chains over 16 rows
        float add = 0.f, sub = 0.f;
        #pragma unroll
        for (int rr = 0; rr < ROWS; ++rr) {
            const int r = r0 + rr;
            float v = (ix + add) - sub;
            s_v[rr * VSTRIDE + 16 + c] = (unsigned char)__float2int_rn(v * QS);
            int ar = r + KR + 1;
            int sr = r - KR;
            if (ar < H)  add += __ldcg(&mb[ar * W + c]);
            if (sr >= 0) sub += __ldcg(&mb[sr * W + c]);
        }
    }
    __syncthreads();

    // ================= phase 2: dp4a horizontal box + elementwise ===========
    const int u  = t & 63;              // thread within row (8 cols each)
    const int g0 = t >> 6;              // 0..7

    float a0 = 0.f, a1 = 0.f, a2 = 0.f, a3 = 0.f;

    #pragma unroll
    for (int pass = 0; pass < 2; ++pass) {
        const int lr = pass * 8 + g0;   // local row 0..15
        const int r  = r0 + lr;

        // 5 aligned LDS.64 covering bytes 8u .. 8u+39 of the padded row
        const uint2* vrow = (const uint2*)&s_v[lr * VSTRIDE];
        uint2 L0 = vrow[u + 0];
        uint2 L1 = vrow[u + 1];
        uint2 L2 = vrow[u + 2];
        uint2 L3 = vrow[u + 3];
        uint2 L4 = vrow[u + 4];

        // streaming inputs: mask (L2-resident re-read) + pred (DRAM)
        const float4* mrow = (const float4*)(mb + (size_t)r * W);
        const float4* prow = (const float4*)(pb + (size_t)r * W);
        float4 m4a = mrow[u * 2 + 0];
        float4 m4b = mrow[u * 2 + 1];
        float4 p4a = __ldcg(&prow[u * 2 + 0]);
        float4 p4b = __ldcg(&prow[u * 2 + 1]);

        // integer prefix over 40 bytes via dp4a
        unsigned w0 = L0.x, w1 = L0.y, w8 = L4.x, w9 = L4.y;
        const unsigned M1 = 0x01010101u;
        unsigned wp1 = __dp4a(w0, M1, 0u);
        unsigned wp2 = __dp4a(w1, M1, wp1);
        unsigned wp3 = __dp4a(L1.x, M1, wp2);
        unsigned wp4 = __dp4a(L1.y, M1, wp3);
        unsigned wp5 = __dp4a(L2.x, M1, wp4);
        unsigned wp6 = __dp4a(L2.y, M1, wp5);
        unsigned wp7 = __dp4a(L3.x, M1, wp6);
        unsigned wp8 = __dp4a(L3.y, M1, wp7);
        unsigned wp9 = __dp4a(w8, M1, wp8);

        unsigned loS[8], hiS[8];
        loS[0] = __dp4a(w0, 0x00000001u, 0u);
        loS[1] = __dp4a(w0, 0x00000101u, 0u);
        loS[2] = __dp4a(w0, 0x00010101u, 0u);
        loS[3] = wp1;
        loS[4] = __dp4a(w1, 0x00000001u, wp1);
        loS[5] = __dp4a(w1, 0x00000101u, wp1);
        loS[6] = __dp4a(w1, 0x00010101u, wp1);
        loS[7] = wp2;
        hiS[0] = wp8;
        hiS[1] = __dp4a(w8, 0x00000001u, wp8);
        hiS[2] = __dp4a(w8, 0x00000101u, wp8);
        hiS[3] = __dp4a(w8, 0x00010101u, wp8);
        hiS[4] = wp9;
        hiS[5] = __dp4a(w9, 0x00000001u, wp9);
        hiS[6] = __dp4a(w9, 0x00000101u, wp9);
        hiS[7] = __dp4a(w9, 0x00010101u, wp9);

        float mv[8] = {m4a.x, m4a.y, m4a.z, m4a.w, m4b.x, m4b.y, m4b.z, m4b.w};
        float pv[8] = {p4a.x, p4a.y, p4a.z, p4a.w, p4b.x, p4b.y, p4b.z, p4b.w};

        #pragma unroll
        for (int i = 0; i < 8; ++i) {
            float box  = (float)(int)(hiS[i] - loS[i]) * BOXSCALE;
            float m    = mv[i];
            float p    = pv[i];
            float weit = 1.0f + MUF * fabsf(box - m);

            float eexp = __expf(-fabsf(p));
            float bce  = fmaxf(p, 0.0f) - p * m + __logf(1.0f + eexp);
            float rcp  = __fdividef(1.0f, 1.0f + eexp);
            float ps   = (p >= 0.0f) ? rcp : eexp * rcp;

            a0 += weit * bce;
            a1 += weit;
            float wps = weit * ps;
            a2 += wps * m;
            a3 += wps + weit * m;
        }
    }

    // ---- warp reduction ----
    const int wid  = t >> 5;
    const int lane = t & 31;
    #pragma unroll
    for (int d = 16; d > 0; d >>= 1) {
        a0 += __shfl_down_sync(0xffffffffu, a0, d);
        a1 += __shfl_down_sync(0xffffffffu, a1, d);
        a2 += __shfl_down_sync(0xffffffffu, a2, d);
        a3 += __shfl_down_sync(0xffffffffu, a3, d);
    }
    if (lane == 0) {
        red[wid * 4 + 0] = a0;
        red[wid * 4 + 1] = a1;
        red[wid * 4 + 2] = a2;
        red[wid * 4 + 3] = a3;
    }
    __syncthreads();

    // ---- cross-warp reduction: warps 0,1 (lane = w*4+k over 16 warps) ----
    if (t < 64) {
        float y = red[t];
        y += __shfl_xor_sync(0xffffffffu, y, 4);    // within each 32-lane group
        y += __shfl_xor_sync(0xffffffffu, y, 8);
        y += __shfl_xor_sync(0xffffffffu, y, 16);
        // lanes 0..3 of each warp hold sums of that warp's 8 warp-groups
        if ((t & 31) < 4) red[(t >> 5) * 4 + (t & 3)] = y;
    }
    __syncthreads();
    if (t == 0) {
        float s0 = red[0] + red[4];
        float s1 = red[1] + red[5];
        float s2 = red[2] + red[6];
        float s3 = red[3] + red[7];
        __stcg(&g_part4[blockIdx.x], make_float4(s0, s1, s2, s3));
        unsigned int old;
        asm volatile("atom.acq_rel.gpu.global.add.u32 %0, [%1], %2;"
                     : "=r"(old) : "l"(&g_count), "r"(1u) : "memory");
        flag = (old == NBLK - 1) ? 1.f : 0.f;
    }
    __syncthreads();

    // ---------- last block finalizes ----------
    if (flag != 0.f) {
        if (t < 128) {
            const int bb = t >> 3;      // batch 0..15
            const int j  = t & 7;       // chunk 0..7 (4 blocks each)
            float s0 = 0.f, s1 = 0.f, s2 = 0.f, s3 = 0.f;
            const float4* gp = g_part4 + bb * 32 + j * 4;
            #pragma unroll
            for (int kk = 0; kk < 4; ++kk) {
                float4 vv = __ldcg(&gp[kk]);
                s0 += vv.x; s1 += vv.y; s2 += vv.z; s3 += vv.w;
            }
            #pragma unroll
            for (int d = 4; d > 0; d >>= 1) {
                s0 += __shfl_down_sync(0xffffffffu, s0, d, 8);
                s1 += __shfl_down_sync(0xffffffffu, s1, d, 8);
                s2 += __shfl_down_sync(0xffffffffu, s2, d, 8);
                s3 += __shfl_down_sync(0xffffffffu, s3, d, 8);
            }
            if (j == 0) {
                float wbce = s0 / s1;
                float wiou = 1.0f - (s2 + 1.0f) / (s3 - s2 + 1.0f);
                red[bb] = wbce + wiou;
            }
        }
        __syncthreads();
        if (t == 0) {
            float s = 0.f;
            #pragma unroll
            for (int kk = 0; kk < NB; ++kk) s += red[kk];
            out[0] = s * (1.0f / NB);
            g_count = 0;                // self-reset for next graph replay
        }
    }
}

extern "C" void kernel_launch(void* const* d_in, const int* in_sizes, int n_in,
                              void* d_out, int out_size) {
    const float* pred = (const float*)d_in[0];
    const float* mask = (const float*)d_in[1];
    if (n_in >= 2 && in_sizes[0] == NB * H * W && in_sizes[1] == NB * 2 * H * W) {
        mask = (const float*)d_in[0];
        pred = (const float*)d_in[1];
    }
    float* out = (float*)d_out;

    fused_kernel<<<NBLK, 512>>>(pred, mask, out);
}

// round 13
// speedup vs baseline: 1.1392x; 1.0639x over previous
#include <cuda_runtime.h>
#include <math.h>

#define NB 16
#define H 512
#define W 512
#define KR 15
#define MUF 5.0f
#define QS 8.0f                       // vsum quant scale
#define BOXSCALE (1.0f/(961.0f*8.0f)) // KKINV / QS
#define RPB 16                        // rows per vert strip
#define VSTRIDE 544                   // 16B pad | 512 cols | 16B pad
#define NBLK 1024                     // persistent grid (<= 7/SM, 8 resident cap)

// zero-initialized; vsum pad bytes are never written so they stay 0 forever
__device__ unsigned char g_vu8[NB * H * VSTRIDE];   // ~4.45 MB (L2-resident)
__device__ float4 g_part4[NBLK];                    // per-block partials
__device__ unsigned int g_sync;                     // phase barrier counter
__device__ unsigned int g_count;                    // finalize counter

__global__ void __launch_bounds__(256, 8)
fused_kernel(const float* __restrict__ pred,
             const float* __restrict__ mask,
             float* __restrict__ out) {
    __shared__ float red[32];        // 8 warps x 4 accumulators
    __shared__ float flag;

    const int t = threadIdx.x;       // 0..255

    // ================= Phase A: vertical sliding box sum -> g_vu8 ==========
    // 1024 blocks: strip s = blockIdx/2 (16 rows), column half = blockIdx&1.
    {
        const int s  = blockIdx.x >> 1;          // 0..511
        const int b  = s >> 5;
        const int r0 = (s & 31) * RPB;
        const int c  = ((blockIdx.x & 1) << 8) + t;   // 0..511

        const float* mb = mask + (size_t)b * H * W;
        unsigned char* vb = g_vu8 + (size_t)b * H * VSTRIDE + 16 + c;

        // 4-way tree init of window [r0-15, r0+15]  (r0+15 <= 511)
        float a0 = 0.f, a1 = 0.f, a2 = 0.f, a3 = 0.f;
        int lo = r0 - KR; if (lo < 0) lo = 0;
        const int hi = r0 + KR;
        int k = 0;
        for (int j = lo; j <= hi; ++j, ++k) {
            float v = mb[j * W + c];             // default caching: warm L2 for phase B
            if ((k & 3) == 0) a0 += v;
            else if ((k & 3) == 1) a1 += v;
            else if ((k & 3) == 2) a2 += v;
            else a3 += v;
        }
        const float ix = (a0 + a1) + (a2 + a3);

        float add = 0.f, sub = 0.f;
        #pragma unroll
        for (int rr = 0; rr < RPB; ++rr) {
            const int r = r0 + rr;
            float v = (ix + add) - sub;
            vb[r * VSTRIDE] = (unsigned char)__float2int_rn(v * QS);
            int ar = r + KR + 1;
            int sr = r - KR;
            if (ar < H)  add += mb[ar * W + c];
            if (sr >= 0) sub += mb[sr * W + c];
        }
    }

    // ================= grid barrier (all 1024 blocks resident) ==============
    __syncthreads();
    if (t == 0) {
        unsigned int old;
        asm volatile("atom.acq_rel.gpu.global.add.u32 %0, [%1], %2;"
                     : "=r"(old) : "l"(&g_sync), "r"(1u) : "memory");
        if (old != NBLK - 1) {
            unsigned int v;
            do {
                __nanosleep(64);
                asm volatile("ld.global.acquire.gpu.u32 %0, [%1];"
                             : "=r"(v) : "l"(&g_sync) : "memory");
            } while (v < NBLK);
        }
    }
    __syncthreads();

    // ================= Phase B: dp4a horizontal box + elementwise ===========
    // block handles 8 rows in 2 passes of 4 rows; 64 threads/row, 8 cols/thread
    const int u  = t & 63;
    const int g  = t >> 6;              // 0..3

    float a0 = 0.f, a1 = 0.f, a2 = 0.f, a3 = 0.f;

    #pragma unroll
    for (int pass = 0; pass < 2; ++pass) {
        const int rowg = blockIdx.x * 8 + pass * 4 + g;   // 0..8191
        const int b = rowg >> 9;
        const int r = rowg & (H - 1);

        // vsum halo: bytes 8u .. 8u+39 as 5 aligned LDG.64 (L2 hits)
        const uint2* vrow = (const uint2*)(g_vu8 + ((size_t)b * H + r) * VSTRIDE);
        uint2 L0 = vrow[u + 0];
        uint2 L1 = vrow[u + 1];
        uint2 L2 = vrow[u + 2];
        uint2 L3 = vrow[u + 3];
        uint2 L4 = vrow[u + 4];

        // streaming inputs: fp32 mask (L2-hot) + fp32 pred (DRAM)
        const size_t rowOff = ((size_t)b * H + r) * W;
        const float4* mrow = (const float4*)(mask + rowOff);
        const size_t predOff = (((size_t)b * 2 + 1) * H + r) * W;
        const float4* prow = (const float4*)(pred + predOff);
        float4 m4a = mrow[u * 2 + 0];
        float4 m4b = mrow[u * 2 + 1];
        float4 p4a = __ldcg(&prow[u * 2 + 0]);
        float4 p4b = __ldcg(&prow[u * 2 + 1]);

        // integer prefix over 40 bytes via dp4a
        unsigned w0 = L0.x, w1 = L0.y, w8 = L4.x, w9 = L4.y;
        const unsigned M1 = 0x01010101u;
        unsigned wp1 = __dp4a(w0, M1, 0u);
        unsigned wp2 = __dp4a(w1, M1, wp1);
        unsigned wp3 = __dp4a(L1.x, M1, wp2);
        unsigned wp4 = __dp4a(L1.y, M1, wp3);
        unsigned wp5 = __dp4a(L2.x, M1, wp4);
        unsigned wp6 = __dp4a(L2.y, M1, wp5);
        unsigned wp7 = __dp4a(L3.x, M1, wp6);
        unsigned wp8 = __dp4a(L3.y, M1, wp7);
        unsigned wp9 = __dp4a(w8, M1, wp8);

        unsigned loS[8], hiS[8];
        loS[0] = __dp4a(w0, 0x00000001u, 0u);
        loS[1] = __dp4a(w0, 0x00000101u, 0u);
        loS[2] = __dp4a(w0, 0x00010101u, 0u);
        loS[3] = wp1;
        loS[4] = __dp4a(w1, 0x00000001u, wp1);
        loS[5] = __dp4a(w1, 0x00000101u, wp1);
        loS[6] = __dp4a(w1, 0x00010101u, wp1);
        loS[7] = wp2;
        hiS[0] = wp8;
        hiS[1] = __dp4a(w8, 0x00000001u, wp8);
        hiS[2] = __dp4a(w8, 0x00000101u, wp8);
        hiS[3] = __dp4a(w8, 0x00010101u, wp8);
        hiS[4] = wp9;
        hiS[5] = __dp4a(w9, 0x00000001u, wp9);
        hiS[6] = __dp4a(w9, 0x00000101u, wp9);
        hiS[7] = __dp4a(w9, 0x00010101u, wp9);

        float mv[8] = {m4a.x, m4a.y, m4a.z, m4a.w, m4b.x, m4b.y, m4b.z, m4b.w};
        float pv[8] = {p4a.x, p4a.y, p4a.z, p4a.w, p4b.x, p4b.y, p4b.z, p4b.w};

        #pragma unroll
        for (int i = 0; i < 8; ++i) {
            float box  = (float)(int)(hiS[i] - loS[i]) * BOXSCALE;
            float m    = mv[i];
            float p    = pv[i];
            float weit = 1.0f + MUF * fabsf(box - m);

            float eexp = __expf(-fabsf(p));
            float bce  = fmaxf(p, 0.0f) - p * m + __logf(1.0f + eexp);
            float rcp  = __fdividef(1.0f, 1.0f + eexp);
            float ps   = (p >= 0.0f) ? rcp : eexp * rcp;

            a0 += weit * bce;
            a1 += weit;
            float wps = weit * ps;
            a2 += wps * m;
            a3 += wps + weit * m;
        }
    }

    // ---- warp reduction ----
    const int wid  = t >> 5;
    const int lane = t & 31;
    #pragma unroll
    for (int d = 16; d > 0; d >>= 1) {
        a0 += __shfl_down_sync(0xffffffffu, a0, d);
        a1 += __shfl_down_sync(0xffffffffu, a1, d);
        a2 += __shfl_down_sync(0xffffffffu, a2, d);
        a3 += __shfl_down_sync(0xffffffffu, a3, d);
    }
    if (lane == 0) {
        red[wid * 4 + 0] = a0;
        red[wid * 4 + 1] = a1;
        red[wid * 4 + 2] = a2;
        red[wid * 4 + 3] = a3;
    }
    __syncthreads();

    // ---- cross-warp reduction in warp 0 (shuffle tree) ----
    if (wid == 0) {
        float y = red[lane];                 // lane = w*4 + k, w<8, k<4
        y += __shfl_xor_sync(0xffffffffu, y, 4);
        y += __shfl_xor_sync(0xffffffffu, y, 8);
        y += __shfl_xor_sync(0xffffffffu, y, 16);
        float s0 = __shfl_sync(0xffffffffu, y, 0);
        float s1 = __shfl_sync(0xffffffffu, y, 1);
        float s2 = __shfl_sync(0xffffffffu, y, 2);
        float s3 = __shfl_sync(0xffffffffu, y, 3);
        if (lane == 0) {
            __stcg(&g_part4[blockIdx.x], make_float4(s0, s1, s2, s3));
            unsigned int old;
            asm volatile("atom.acq_rel.gpu.global.add.u32 %0, [%1], %2;"
                         : "=r"(old) : "l"(&g_count), "r"(1u) : "memory");
            flag = (old == NBLK - 1) ? 1.f : 0.f;
        }
    }
    __syncthreads();

    // ---------- last block finalizes ----------
    if (flag != 0.f) {
        if (t < 128) {
            const int bb = t >> 3;           // batch 0..15
            const int j  = t & 7;            // chunk 0..7 (8 blocks each)
            float s0 = 0.f, s1 = 0.f, s2 = 0.f, s3 = 0.f;
            const float4* gp = g_part4 + bb * (NBLK / NB) + j * 8;
            #pragma unroll
            for (int kk = 0; kk < 8; ++kk) {
                float4 vv = __ldcg(&gp[kk]);
                s0 += vv.x; s1 += vv.y; s2 += vv.z; s3 += vv.w;
            }
            #pragma unroll
            for (int d = 4; d > 0; d >>= 1) {
                s0 += __shfl_down_sync(0xffffffffu, s0, d, 8);
                s1 += __shfl_down_sync(0xffffffffu, s1, d, 8);
                s2 += __shfl_down_sync(0xffffffffu, s2, d, 8);
                s3 += __shfl_down_sync(0xffffffffu, s3, d, 8);
            }
            if (j == 0) {
                float wbce = s0 / s1;
                float wiou = 1.0f - (s2 + 1.0f) / (s3 - s2 + 1.0f);
                red[bb] = wbce + wiou;
            }
        }
        __syncthreads();
        if (t == 0) {
            float s = 0.f;
            #pragma unroll
            for (int kk = 0; kk < NB; ++kk) s += red[kk];
            out[0] = s * (1.0f / NB);
            g_count = 0;                     // self-reset for next graph replay
            g_sync  = 0;
        }
    }
}

extern "C" void kernel_launch(void* const* d_in, const int* in_sizes, int n_in,
                              void* d_out, int out_size) {
    const float* pred = (const float*)d_in[0];
    const float* mask = (const float*)d_in[1];
    if (n_in >= 2 && in_sizes[0] == NB * H * W && in_sizes[1] == NB * 2 * H * W) {
        mask = (const float*)d_in[0];
        pred = (const float*)d_in[1];
    }
    float* out = (float*)d_out;

    fused_kernel<<<NBLK, 256>>>(pred, mask, out);
}

// round 14
// speedup vs baseline: 1.3808x; 1.2121x over previous
#include <cuda_runtime.h>
#include <math.h>

#define NB 16
#define H 512
#define W 512
#define KR 15
#define MUF 5.0f
#define QS 8.0f                       // vsum quant scale
#define BOXSCALE (1.0f/(961.0f*8.0f)) // KKINV / QS
#define ROWS 8                        // rows per block
#define VSTRIDE 544                   // 16B pad | 512 cols | 16B pad
#define NBLK (NB * (H / ROWS))        // 1024 blocks

__device__ float4 g_part4[NBLK];      // per-block partials
__device__ unsigned int g_count;      // zero-init; self-resetting

__global__ void __launch_bounds__(256, 7)
fused_kernel(const float* __restrict__ pred,
             const float* __restrict__ mask,
             float* __restrict__ out) {
    __shared__ unsigned char s_v[ROWS * VSTRIDE];   // u8 vsums, padded rows (4.3KB)
    __shared__ float red[32];                       // 8 warps x 4
    __shared__ float flag;

    const int t  = threadIdx.x;         // 0..255
    const int b  = blockIdx.x >> 6;     // batch
    const int r0 = (blockIdx.x & 63) * ROWS;

    const float* mb = mask + (size_t)b * H * W;
    const float* pb = pred + (size_t)(b * 2 + 1) * H * W;   // channel-1 logits

    // ---- zero smem pads: 8 rows x 8 words (4 left, 4 right) = 64 words ----
    if (t < 64) {
        const int row = t >> 3;
        const int idx = t & 7;
        const int off = row * VSTRIDE + (idx < 4 ? idx * 4 : 528 + (idx - 4) * 4);
        *(unsigned int*)&s_v[off] = 0u;
    }

    // ========== Phase A: vertical sliding box sum -> smem u8 (block-local) ==
    {
        const float2* mb2 = (const float2*)mb;
        const int c = t;                // owns cols 2c, 2c+1

        // 4-way tree init of window [r0-15, r0+15] (<= 31 independent loads)
        float ax[4] = {0.f, 0.f, 0.f, 0.f};
        float ay[4] = {0.f, 0.f, 0.f, 0.f};
        int lo = r0 - KR; if (lo < 0) lo = 0;
        const int hi = r0 + KR;         // <= 511
        int k = 0;
        for (int j = lo; j <= hi; ++j, ++k) {
            float2 v = mb2[j * (W / 2) + c];
            ax[k & 3] += v.x; ay[k & 3] += v.y;
        }
        const float ix = (ax[0] + ax[1]) + (ax[2] + ax[3]);
        const float iy = (ay[0] + ay[1]) + (ay[2] + ay[3]);

        // independent add / sub chains over 8 rows
        float addx = 0.f, addy = 0.f, subx = 0.f, suby = 0.f;
        #pragma unroll
        for (int rr = 0; rr < ROWS; ++rr) {
            const int r = r0 + rr;
            float vx = (ix + addx) - subx;
            float vy = (iy + addy) - suby;
            unsigned qx = (unsigned)__float2int_rn(vx * QS);
            unsigned qy = (unsigned)__float2int_rn(vy * QS);
            *(unsigned short*)&s_v[rr * VSTRIDE + 16 + 2 * c] =
                (unsigned short)(qx | (qy << 8));
            int ar = r + KR + 1;
            int sr = r - KR;
            if (ar < H) {
                float2 v = mb2[ar * (W / 2) + c];
                addx += v.x; addy += v.y;
            }
            if (sr >= 0) {
                float2 v = mb2[sr * (W / 2) + c];
                subx += v.x; suby += v.y;
            }
        }
    }
    __syncthreads();

    // ========== Phase B: dp4a horizontal box + elementwise ==================
    const int u = t & 63;               // thread within row (8 cols each)
    const int g = t >> 6;               // 0..3

    float a0 = 0.f, a1 = 0.f, a2 = 0.f, a3 = 0.f;

    #pragma unroll
    for (int pass = 0; pass < 2; ++pass) {
        const int lr = pass * 4 + g;    // local row 0..7
        const int r  = r0 + lr;

        // 5 aligned LDS.64 covering bytes 8u .. 8u+39 of the padded row
        const uint2* vrow = (const uint2*)&s_v[lr * VSTRIDE];
        uint2 L0 = vrow[u + 0];
        uint2 L1 = vrow[u + 1];
        uint2 L2 = vrow[u + 2];
        uint2 L3 = vrow[u + 3];
        uint2 L4 = vrow[u + 4];

        // streaming inputs: fp32 mask (L1/L2-hot from phase A) + pred (DRAM)
        const float4* mrow = (const float4*)(mb + (size_t)r * W);
        const float4* prow = (const float4*)(pb + (size_t)r * W);
        float4 m4a = mrow[u * 2 + 0];
        float4 m4b = mrow[u * 2 + 1];
        float4 p4a = __ldcg(&prow[u * 2 + 0]);
        float4 p4b = __ldcg(&prow[u * 2 + 1]);

        // integer prefix over 40 bytes via dp4a
        unsigned w0 = L0.x, w1 = L0.y, w8 = L4.x, w9 = L4.y;
        const unsigned M1 = 0x01010101u;
        unsigned wp1 = __dp4a(w0, M1, 0u);
        unsigned wp2 = __dp4a(w1, M1, wp1);
        unsigned wp3 = __dp4a(L1.x, M1, wp2);
        unsigned wp4 = __dp4a(L1.y, M1, wp3);
        unsigned wp5 = __dp4a(L2.x, M1, wp4);
        unsigned wp6 = __dp4a(L2.y, M1, wp5);
        unsigned wp7 = __dp4a(L3.x, M1, wp6);
        unsigned wp8 = __dp4a(L3.y, M1, wp7);
        unsigned wp9 = __dp4a(w8, M1, wp8);

        unsigned loS[8], hiS[8];
        loS[0] = __dp4a(w0, 0x00000001u, 0u);
        loS[1] = __dp4a(w0, 0x00000101u, 0u);
        loS[2] = __dp4a(w0, 0x00010101u, 0u);
        loS[3] = wp1;
        loS[4] = __dp4a(w1, 0x00000001u, wp1);
        loS[5] = __dp4a(w1, 0x00000101u, wp1);
        loS[6] = __dp4a(w1, 0x00010101u, wp1);
        loS[7] = wp2;
        hiS[0] = wp8;
        hiS[1] = __dp4a(w8, 0x00000001u, wp8);
        hiS[2] = __dp4a(w8, 0x00000101u, wp8);
        hiS[3] = __dp4a(w8, 0x00010101u, wp8);
        hiS[4] = wp9;
        hiS[5] = __dp4a(w9, 0x00000001u, wp9);
        hiS[6] = __dp4a(w9, 0x00000101u, wp9);
        hiS[7] = __dp4a(w9, 0x00010101u, wp9);

        float mv[8] = {m4a.x, m4a.y, m4a.z, m4a.w, m4b.x, m4b.y, m4b.z, m4b.w};
        float pv[8] = {p4a.x, p4a.y, p4a.z, p4a.w, p4b.x, p4b.y, p4b.z, p4b.w};

        #pragma unroll
        for (int i = 0; i < 8; ++i) {
            float box  = (float)(int)(hiS[i] - loS[i]) * BOXSCALE;
            float m    = mv[i];
            float p    = pv[i];
            float weit = 1.0f + MUF * fabsf(box - m);

            float eexp = __expf(-fabsf(p));
            float bce  = fmaxf(p, 0.0f) - p * m + __logf(1.0f + eexp);
            float rcp  = __fdividef(1.0f, 1.0f + eexp);
            float ps   = (p >= 0.0f) ? rcp : eexp * rcp;

            a0 += weit * bce;
            a1 += weit;
            float wps = weit * ps;
            a2 += wps * m;
            a3 += wps + weit * m;
        }
    }

    // ---- warp reduction ----
    const int wid  = t >> 5;
    const int lane = t & 31;
    #pragma unroll
    for (int d = 16; d > 0; d >>= 1) {
        a0 += __shfl_down_sync(0xffffffffu, a0, d);
        a1 += __shfl_down_sync(0xffffffffu, a1, d);
        a2 += __shfl_down_sync(0xffffffffu, a2, d);
        a3 += __shfl_down_sync(0xffffffffu, a3, d);
    }
    if (lane == 0) {
        red[wid * 4 + 0] = a0;
        red[wid * 4 + 1] = a1;
        red[wid * 4 + 2] = a2;
        red[wid * 4 + 3] = a3;
    }
    __syncthreads();

    // ---- cross-warp reduction in warp 0 (shuffle tree) ----
    if (wid == 0) {
        float y = red[lane];                 // lane = w*4 + k, w<8, k<4
        y += __shfl_xor_sync(0xffffffffu, y, 4);
        y += __shfl_xor_sync(0xffffffffu, y, 8);
        y += __shfl_xor_sync(0xffffffffu, y, 16);
        float s0 = __shfl_sync(0xffffffffu, y, 0);
        float s1 = __shfl_sync(0xffffffffu, y, 1);
        float s2 = __shfl_sync(0xffffffffu, y, 2);
        float s3 = __shfl_sync(0xffffffffu, y, 3);
        if (lane == 0) {
            __stcg(&g_part4[blockIdx.x], make_float4(s0, s1, s2, s3));
            unsigned int old;
            asm volatile("atom.acq_rel.gpu.global.add.u32 %0, [%1], %2;"
                         : "=r"(old) : "l"(&g_count), "r"(1u) : "memory");
            flag = (old == NBLK - 1) ? 1.f : 0.f;
        }
    }
    __syncthreads();

    // ---------- last block finalizes ----------
    if (flag != 0.f) {
        if (t < 128) {
            const int bb = t >> 3;           // batch 0..15
            const int j  = t & 7;            // chunk 0..7 (8 blocks each)
            float s0 = 0.f, s1 = 0.f, s2 = 0.f, s3 = 0.f;
            const float4* gp = g_part4 + bb * (NBLK / NB) + j * 8;
            #pragma unroll
            for (int kk = 0; kk < 8; ++kk) {
                float4 vv = __ldcg(&gp[kk]);
                s0 += vv.x; s1 += vv.y; s2 += vv.z; s3 += vv.w;
            }
            #pragma unroll
            for (int d = 4; d > 0; d >>= 1) {
                s0 += __shfl_down_sync(0xffffffffu, s0, d, 8);
                s1 += __shfl_down_sync(0xffffffffu, s1, d, 8);
                s2 += __shfl_down_sync(0xffffffffu, s2, d, 8);
                s3 += __shfl_down_sync(0xffffffffu, s3, d, 8);
            }
            if (j == 0) {
                float wbce = s0 / s1;
                float wiou = 1.0f - (s2 + 1.0f) / (s3 - s2 + 1.0f);
                red[bb] = wbce + wiou;
            }
        }
        __syncthreads();
        if (t == 0) {
            float s = 0.f;
            #pragma unroll
            for (int kk = 0; kk < NB; ++kk) s += red[kk];
            out[0] = s * (1.0f / NB);
            g_count = 0;                     // self-reset for next graph replay
        }
    }
}

extern "C" void kernel_launch(void* const* d_in, const int* in_sizes, int n_in,
                              void* d_out, int out_size) {
    const float* pred = (const float*)d_in[0];
    const float* mask = (const float*)d_in[1];
    if (n_in >= 2 && in_sizes[0] == NB * H * W && in_sizes[1] == NB * 2 * H * W) {
        mask = (const float*)d_in[0];
        pred = (const float*)d_in[1];
    }
    float* out = (float*)d_out;

    fused_kernel<<<NBLK, 256>>>(pred, mask, out);
}